// round 15
// baseline (speedup 1.0000x reference)
#include <cuda_runtime.h>
#include <cuda_fp16.h>
#include <cstdint>

// ---------------------------------------------------------------------------
// B=16, C=1024, N=1024, T=77(pad 80), heads=8, hd=128.
//   big GEMMs (Q, Y): 256x128x128 tiles, 2 smem stages, 512 thr, 16 warps
//     (8 barrier/wait pairs per CTA total; 4096-cyc compute per stage)
//   KV: 128x128x32 small GEMM
//   fused attention: S=Q^T K -> register quad-shuffle softmax -> O=V P^T
// Scratch fp16; cols 77..79 stored zero.
// KV head split: K_h rows [256h,256h+128), V_h rows [256h+128,256h+256).
// ---------------------------------------------------------------------------

#define NB 16
#define CC 1024
#define NN 1024
#define TT 77
#define TP 80
#define NH 8
#define HD 128

__device__ __half h_Vx[(size_t)NB * CC * NN];
__device__ __half h_Tx[(size_t)NB * CC * TP];
__device__ __half h_Wq[(size_t)CC * CC];
__device__ __half h_Wkv[(size_t)2 * CC * CC];
__device__ __half h_Wp[(size_t)CC * CC];
__device__ __half h_Q [(size_t)NB * CC * NN];
__device__ __half h_KV[(size_t)NB * 2 * CC * TP];
__device__ __half h_O [(size_t)NB * CC * NN];

__device__ __forceinline__ uint32_t smem_u32(const void* p) {
    uint32_t a;
    asm("{ .reg .u64 t; cvta.to.shared.u64 t, %1; cvt.u32.u64 %0, t; }" : "=r"(a) : "l"(p));
    return a;
}
#define CP16(d, s, sz) asm volatile("cp.async.cg.shared.global [%0], [%1], 16, %2;" :: "r"(d), "l"(s), "r"(sz) : "memory")
#define CP_COMMIT()    asm volatile("cp.async.commit_group;" ::: "memory")
#define CP_WAIT1()     asm volatile("cp.async.wait_group 1;" ::: "memory")
#define CP_WAIT0()     asm volatile("cp.async.wait_group 0;" ::: "memory")

#define LDSM_X4(r0, r1, r2, r3, a) \
    asm volatile("ldmatrix.sync.aligned.m8n8.x4.shared.b16 {%0,%1,%2,%3}, [%4];" \
        : "=r"(r0), "=r"(r1), "=r"(r2), "=r"(r3) : "r"(a))
#define LDSM_X4T(r0, r1, r2, r3, a) \
    asm volatile("ldmatrix.sync.aligned.m8n8.x4.trans.shared.b16 {%0,%1,%2,%3}, [%4];" \
        : "=r"(r0), "=r"(r1), "=r"(r2), "=r"(r3) : "r"(a))

__device__ __forceinline__ void mma_f16(float* c, const uint32_t* a, const uint32_t* b) {
    asm volatile(
        "mma.sync.aligned.m16n8k16.row.col.f32.f16.f16.f32 "
        "{%0,%1,%2,%3}, {%4,%5,%6,%7}, {%8,%9}, {%0,%1,%2,%3};\n"
        : "+f"(c[0]), "+f"(c[1]), "+f"(c[2]), "+f"(c[3])
        : "r"(a[0]), "r"(a[1]), "r"(a[2]), "r"(a[3]), "r"(b[0]), "r"(b[1]));
}

// ===========================================================================
// BIG GEMM: 256x128x128 tiles, 2 stages, 512 thr = 16 warps (4m x 4n),
// warp tile 64x32.  A [m][136]h pitch, B [k][136]h pitch (both 272B,
// conflict-free for ldmatrix).  OM: 0 = fp32 out, 1 = fp16 out.
// Loop: wait0 -> sync -> issue load(kt+1) -> 4096 cyc of MMA.  8 iters.
// ===========================================================================
#define BIG_A_B 69632                      // 256*136*2
#define BIG_B_B 34816                      // 128*136*2
#define BIG_STAGE (BIG_A_B + BIG_B_B)      // 104448
#define BIG_SMEM (BIG_STAGE * 2)           // 208896

template <int OM>
__global__ __launch_bounds__(512, 1)
void hgemm_big(const __half* __restrict__ A, const __half* __restrict__ B,
               void* __restrict__ Cv, const float* __restrict__ bias,
               long long sBb, long long sCb)
{
    extern __shared__ char smem[];
    const uint32_t sb = smem_u32(smem);

    const int tid  = threadIdx.x;
    const int lane = tid & 31;
    const int warp = tid >> 5;
    const int wm = (warp & 3) * 64;
    const int wn = (warp >> 2) * 32;
    const int gid = lane >> 2;
    const int tig = lane & 3;
    const int tl  = lane >> 3;
    const int rr  = lane & 7;

    const int m0 = blockIdx.y * 256;
    const int n0 = blockIdx.x * 128;
    const __half* Bb = B + (size_t)blockIdx.z * sBb;

    auto load_tile = [&](int kt, int s) {
        const int k0 = kt << 7;
        const uint32_t aB = sb + (uint32_t)s * BIG_STAGE;
        const uint32_t bB = aB + BIG_A_B;
        #pragma unroll
        for (int i = 0; i < 8; i++) {                    // A: 256m x 128k
            int sg = tid + i * 512;
            int m = sg >> 4, seg = sg & 15;
            CP16(aB + (uint32_t)(m * 136 + seg * 8) * 2,
                 A + (size_t)(m0 + m) * CC + k0 + seg * 8, 16);
        }
        #pragma unroll
        for (int i = 0; i < 4; i++) {                    // B: 128k x 128n
            int sg = tid + i * 512;
            int k = sg >> 4, sn = sg & 15;
            CP16(bB + (uint32_t)(k * 136 + sn * 8) * 2,
                 Bb + (size_t)(k0 + k) * NN + n0 + sn * 8, 16);
        }
        CP_COMMIT();
    };

    float acc[4][4][4];
    #pragma unroll
    for (int mi = 0; mi < 4; mi++)
        #pragma unroll
        for (int ni = 0; ni < 4; ni++)
            #pragma unroll
            for (int j = 0; j < 4; j++) acc[mi][ni][j] = 0.f;

    load_tile(0, 0);

    const int nkt = CC >> 7;                 // 8
    for (int kt = 0; kt < nkt; kt++) {
        CP_WAIT0();                          // load(kt) done (only pending group)
        __syncthreads();                     // all warps past stage (kt+1)%2 reads
        if (kt + 1 < nkt) load_tile(kt + 1, (kt + 1) & 1);

        const uint32_t aB = sb + (uint32_t)((kt & 1) * BIG_STAGE);
        const uint32_t bB = aB + BIG_A_B;

        #pragma unroll
        for (int kk = 0; kk < 128; kk += 16) {
            uint32_t afr[4][4], bfr[4][2];
            #pragma unroll
            for (int mi = 0; mi < 4; mi++) {
                uint32_t addr = aB + (uint32_t)((wm + mi * 16 + (tl & 1) * 8 + rr) * 136
                                                + kk + (tl >> 1) * 8) * 2;
                LDSM_X4(afr[mi][0], afr[mi][1], afr[mi][2], afr[mi][3], addr);
            }
            #pragma unroll
            for (int np = 0; np < 2; np++) {
                uint32_t addr = bB + (uint32_t)((kk + (tl & 1) * 8 + rr) * 136
                                                + wn + np * 16 + (tl >> 1) * 8) * 2;
                LDSM_X4T(bfr[2*np][0], bfr[2*np][1], bfr[2*np+1][0], bfr[2*np+1][1], addr);
            }
            #pragma unroll
            for (int mi = 0; mi < 4; mi++)
                #pragma unroll
                for (int ni = 0; ni < 4; ni++)
                    mma_f16(acc[mi][ni], afr[mi], bfr[ni]);
        }
    }

    #pragma unroll
    for (int mi = 0; mi < 4; mi++) {
        int r0 = m0 + wm + mi * 16 + gid;
        float bv0 = bias[r0];
        float bv1 = bias[r0 + 8];
        #pragma unroll
        for (int ni = 0; ni < 4; ni++) {
            int c0 = n0 + wn + ni * 8 + 2 * tig;
            if (OM == 0) {
                float* Cb = (float*)Cv + (size_t)blockIdx.z * sCb;
                Cb[(size_t)r0 * NN + c0]           = acc[mi][ni][0] + bv0;
                Cb[(size_t)r0 * NN + c0 + 1]       = acc[mi][ni][1] + bv0;
                Cb[(size_t)(r0 + 8) * NN + c0]     = acc[mi][ni][2] + bv1;
                Cb[(size_t)(r0 + 8) * NN + c0 + 1] = acc[mi][ni][3] + bv1;
            } else {
                __half* Cb = (__half*)Cv + (size_t)blockIdx.z * sCb;
                Cb[(size_t)r0 * NN + c0]           = __float2half(acc[mi][ni][0] + bv0);
                Cb[(size_t)r0 * NN + c0 + 1]       = __float2half(acc[mi][ni][1] + bv0);
                Cb[(size_t)(r0 + 8) * NN + c0]     = __float2half(acc[mi][ni][2] + bv1);
                Cb[(size_t)(r0 + 8) * NN + c0 + 1] = __float2half(acc[mi][ni][3] + bv1);
            }
        }
    }
}

// ===========================================================================
// FUSED ATTENTION — unchanged from round 14 (register quad-shuffle softmax).
// smem: sQ [128d][136]h | sK/sP [128][80]h | sV [128][80]h   = 75776 B
// ===========================================================================
#define FA_SQ 0
#define FA_SK 34816
#define FA_SV 55296
#define FA_SMEM 75776

__global__ __launch_bounds__(256, 2)
void fused_attn(const __half* __restrict__ Q, const __half* __restrict__ KV,
                __half* __restrict__ O, float scale)
{
    extern __shared__ char smem[];
    const uint32_t sb = smem_u32(smem);

    const int tid  = threadIdx.x;
    const int lane = tid & 31;
    const int warp = tid >> 5;
    const int gid = lane >> 2;
    const int tig = lane & 3;
    const int tl  = lane >> 3;
    const int rr  = lane & 7;

    const int n0 = blockIdx.x * 128;
    const int z = blockIdx.y;           // b*8 + h
    const int b = z >> 3, h = z & 7;

    const __half* Qb = Q  + (size_t)b * CC * NN + (size_t)(h * HD) * NN;
    const __half* Kb = KV + (size_t)b * 2 * CC * TP + (size_t)(2 * HD * h) * TP;
    const __half* Vb = Kb + (size_t)HD * TP;

    #pragma unroll
    for (int i = 0; i < 8; i++) {       // Q: 128d x 128n
        int c = tid + i * 256;
        int d = c >> 4, o = (c & 15) * 8;
        CP16(sb + FA_SQ + (uint32_t)(d * 136 + o) * 2,
             Qb + (size_t)d * NN + n0 + o, 16);
    }
    #pragma unroll
    for (int i = 0; i < 5; i++) {       // K: 128d x 80t
        int c = tid + i * 256;
        int d = c / 10, o = (c % 10) * 8;
        CP16(sb + FA_SK + (uint32_t)(d * 80 + o) * 2,
             Kb + (size_t)d * TP + o, 16);
    }
    #pragma unroll
    for (int i = 0; i < 5; i++) {       // V: 128d x 80t
        int c = tid + i * 256;
        int d = c / 10, o = (c % 10) * 8;
        CP16(sb + FA_SV + (uint32_t)(d * 80 + o) * 2,
             Vb + (size_t)d * TP + o, 16);
    }
    CP_COMMIT();
    CP_WAIT0();
    __syncthreads();

    {
        const int wm = warp * 16;
        float accs[10][4];
        #pragma unroll
        for (int ni = 0; ni < 10; ni++)
            #pragma unroll
            for (int j = 0; j < 4; j++) accs[ni][j] = 0.f;

        #pragma unroll
        for (int kk = 0; kk < 128; kk += 16) {
            uint32_t afr[4];
            uint32_t aaddr = sb + FA_SQ + (uint32_t)((kk + (tl >> 1) * 8 + rr) * 136
                                                     + wm + (tl & 1) * 8) * 2;
            LDSM_X4T(afr[0], afr[1], afr[2], afr[3], aaddr);
            uint32_t bfr[10][2];
            #pragma unroll
            for (int tb = 0; tb < 5; tb++) {
                uint32_t baddr = sb + FA_SK + (uint32_t)((kk + (tl & 1) * 8 + rr) * 80
                                                         + tb * 16 + (tl >> 1) * 8) * 2;
                LDSM_X4T(bfr[2*tb][0], bfr[2*tb][1], bfr[2*tb+1][0], bfr[2*tb+1][1], baddr);
            }
            #pragma unroll
            for (int ni = 0; ni < 10; ni++)
                mma_f16(accs[ni], afr, bfr[ni]);
        }

        #pragma unroll
        for (int ni = 0; ni < 10; ni++)
            #pragma unroll
            for (int j = 0; j < 4; j++) accs[ni][j] *= scale;

        float mx0 = -1e30f, mx1 = -1e30f;
        #pragma unroll
        for (int ni = 0; ni < 10; ni++) {
            int c0 = ni * 8 + 2 * tig;
            if (c0 < TT)     { mx0 = fmaxf(mx0, accs[ni][0]); mx1 = fmaxf(mx1, accs[ni][2]); }
            if (c0 + 1 < TT) { mx0 = fmaxf(mx0, accs[ni][1]); mx1 = fmaxf(mx1, accs[ni][3]); }
        }
        mx0 = fmaxf(mx0, __shfl_xor_sync(0xFFFFFFFFu, mx0, 1));
        mx0 = fmaxf(mx0, __shfl_xor_sync(0xFFFFFFFFu, mx0, 2));
        mx1 = fmaxf(mx1, __shfl_xor_sync(0xFFFFFFFFu, mx1, 1));
        mx1 = fmaxf(mx1, __shfl_xor_sync(0xFFFFFFFFu, mx1, 2));

        float s0 = 0.f, s1 = 0.f;
        #pragma unroll
        for (int ni = 0; ni < 10; ni++) {
            int c0 = ni * 8 + 2 * tig;
            float e0 = (c0 < TT)     ? __expf(accs[ni][0] - mx0) : 0.f;
            float e1 = (c0 + 1 < TT) ? __expf(accs[ni][1] - mx0) : 0.f;
            float e2 = (c0 < TT)     ? __expf(accs[ni][2] - mx1) : 0.f;
            float e3 = (c0 + 1 < TT) ? __expf(accs[ni][3] - mx1) : 0.f;
            accs[ni][0] = e0; accs[ni][1] = e1; accs[ni][2] = e2; accs[ni][3] = e3;
            s0 += e0 + e1; s1 += e2 + e3;
        }
        s0 += __shfl_xor_sync(0xFFFFFFFFu, s0, 1);
        s0 += __shfl_xor_sync(0xFFFFFFFFu, s0, 2);
        s1 += __shfl_xor_sync(0xFFFFFFFFu, s1, 1);
        s1 += __shfl_xor_sync(0xFFFFFFFFu, s1, 2);
        float inv0 = 1.f / s0, inv1 = 1.f / s1;

        __syncthreads();

        __half* P = (__half*)(smem + FA_SK);
        #pragma unroll
        for (int ni = 0; ni < 10; ni++) {
            int c0 = ni * 8 + 2 * tig;
            *reinterpret_cast<__half2*>(P + (wm + gid) * 80 + c0) =
                __floats2half2_rn(accs[ni][0] * inv0, accs[ni][1] * inv0);
            *reinterpret_cast<__half2*>(P + (wm + gid + 8) * 80 + c0) =
                __floats2half2_rn(accs[ni][2] * inv1, accs[ni][3] * inv1);
        }
    }
    __syncthreads();

    {
        const int wm2 = (warp & 3) * 32;
        const int wn2 = (warp >> 2) * 64;
        float acco[2][8][4];
        #pragma unroll
        for (int mi = 0; mi < 2; mi++)
            #pragma unroll
            for (int ni = 0; ni < 8; ni++)
                #pragma unroll
                for (int j = 0; j < 4; j++) acco[mi][ni][j] = 0.f;

        #pragma unroll
        for (int kk = 0; kk < 80; kk += 16) {
            uint32_t afr[2][4], bfr[8][2];
            #pragma unroll
            for (int mi = 0; mi < 2; mi++) {
                uint32_t addr = sb + FA_SV + (uint32_t)((wm2 + mi * 16 + (tl & 1) * 8 + rr) * 80
                                                        + kk + (tl >> 1) * 8) * 2;
                LDSM_X4(afr[mi][0], afr[mi][1], afr[mi][2], afr[mi][3], addr);
            }
            #pragma unroll
            for (int np = 0; np < 4; np++) {
                uint32_t addr = sb + FA_SK + (uint32_t)((wn2 + np * 16 + (tl >> 1) * 8 + rr) * 80
                                                        + kk + (tl & 1) * 8) * 2;
                LDSM_X4(bfr[2*np][0], bfr[2*np][1], bfr[2*np+1][0], bfr[2*np+1][1], addr);
            }
            #pragma unroll
            for (int mi = 0; mi < 2; mi++)
                #pragma unroll
                for (int ni = 0; ni < 8; ni++)
                    mma_f16(acco[mi][ni], afr[mi], bfr[ni]);
        }

        __half* Ob = O + (size_t)b * CC * NN + (size_t)(h * HD) * NN;
        #pragma unroll
        for (int mi = 0; mi < 2; mi++) {
            int r0 = wm2 + mi * 16 + gid;
            #pragma unroll
            for (int ni = 0; ni < 8; ni++) {
                int c0 = n0 + wn2 + ni * 8 + 2 * tig;
                Ob[(size_t)r0 * NN + c0]           = __float2half(acco[mi][ni][0]);
                Ob[(size_t)r0 * NN + c0 + 1]       = __float2half(acco[mi][ni][1]);
                Ob[(size_t)(r0 + 8) * NN + c0]     = __float2half(acco[mi][ni][2]);
                Ob[(size_t)(r0 + 8) * NN + c0 + 1] = __float2half(acco[mi][ni][3]);
            }
        }
    }
}

// ===========================================================================
// Small generic GEMM — KV projection only (unchanged).
// ===========================================================================
#define STAGE_B 20480

template <bool AT, bool BT, int OM>
__global__ __launch_bounds__(256, 2)
void hgemm(const __half* __restrict__ A, const __half* __restrict__ B,
           void* __restrict__ Cv, const float* __restrict__ bias,
           int M, int N, int K,
           long long sA, long long sB, long long ldc,
           long long sAb, long long sAh, long long sBb, long long sBh,
           long long sCb, long long sCh, int nh, float alpha,
           int Ka, int Bbound, int nvalid)
{
    extern __shared__ char smem[];
    const uint32_t sb = smem_u32(smem);

    const int tid  = threadIdx.x;
    const int lane = tid & 31;
    const int warp = tid >> 5;
    const int wm = (warp & 3) * 32;
    const int wn = (warp >> 2) * 64;
    const int gid = lane >> 2;
    const int tig = lane & 3;
    const int tl  = lane >> 3;
    const int rr  = lane & 7;

    const int z = blockIdx.z;
    const int b = z / nh;
    const int h = z - b * nh;
    const __half* Ab = A + (size_t)b * sAb + (size_t)h * sAh;
    const __half* Bb = B + (size_t)b * sBb + (size_t)h * sBh;

    const int m0 = blockIdx.y * 128;
    const int n0 = blockIdx.x * 128;
    const int nkt = (K + 31) >> 5;

    auto load_tile = [&](int kt, int s) {
        const int k0 = kt << 5;
        const uint32_t aB = sb + (uint32_t)s * STAGE_B;
        const uint32_t bB = aB + 10240;
        #pragma unroll
        for (int i = 0; i < 2; i++) {
            int sg = tid + i * 256;
            if (!AT) {
                int m = sg >> 2, sk = sg & 3;
                CP16(aB + (uint32_t)(m * 40 + sk * 8) * 2,
                     Ab + (size_t)(m0 + m) * sA + k0 + sk * 8,
                     (k0 + sk * 8 < Ka) ? 16 : 0);
            } else {
                int k = sg >> 4, sm = sg & 15;
                CP16(aB + (uint32_t)(k * 136 + sm * 8) * 2,
                     Ab + (size_t)(k0 + k) * sA + m0 + sm * 8, 16);
            }
        }
        #pragma unroll
        for (int i = 0; i < 2; i++) {
            int sg = tid + i * 256;
            if (BT) {
                int k = sg >> 4, sn = sg & 15;
                CP16(bB + (uint32_t)(k * 136 + sn * 8) * 2,
                     Bb + (size_t)(k0 + k) * sB + n0 + sn * 8,
                     (n0 + sn * 8 < Bbound) ? 16 : 0);
            } else {
                int n = sg >> 2, sk = sg & 3;
                CP16(bB + (uint32_t)(n * 40 + sk * 8) * 2,
                     Bb + (size_t)(n0 + n) * sB + k0 + sk * 8,
                     (k0 + sk * 8 < Bbound) ? 16 : 0);
            }
        }
        CP_COMMIT();
    };

    float acc[2][8][4];
    #pragma unroll
    for (int mi = 0; mi < 2; mi++)
        #pragma unroll
        for (int ni = 0; ni < 8; ni++)
            #pragma unroll
            for (int j = 0; j < 4; j++) acc[mi][ni][j] = 0.f;

    load_tile(0, 0);
    if (nkt > 1) load_tile(1, 1); else CP_COMMIT();

    for (int kt = 0; kt < nkt; kt++) {
        CP_WAIT1();
        __syncthreads();
        if (kt + 2 < nkt) load_tile(kt + 2, (kt + 2) % 3);
        else CP_COMMIT();

        const uint32_t aB = sb + (uint32_t)((kt % 3) * STAGE_B);
        const uint32_t bB = aB + 10240;

        #pragma unroll
        for (int kk = 0; kk < 32; kk += 16) {
            uint32_t afr[2][4], bfr[8][2];
            #pragma unroll
            for (int mi = 0; mi < 2; mi++) {
                uint32_t addr;
                if (!AT)
                    addr = aB + (uint32_t)((wm + mi * 16 + (tl & 1) * 8 + rr) * 40
                                           + kk + (tl >> 1) * 8) * 2;
                else
                    addr = aB + (uint32_t)((kk + (tl >> 1) * 8 + rr) * 136
                                           + wm + mi * 16 + (tl & 1) * 8) * 2;
                if (!AT) LDSM_X4 (afr[mi][0], afr[mi][1], afr[mi][2], afr[mi][3], addr);
                else     LDSM_X4T(afr[mi][0], afr[mi][1], afr[mi][2], afr[mi][3], addr);
            }
            #pragma unroll
            for (int np = 0; np < 4; np++) {
                int nb = wn + np * 16;
                uint32_t addr;
                if (BT)
                    addr = bB + (uint32_t)((kk + (tl & 1) * 8 + rr) * 136
                                           + nb + (tl >> 1) * 8) * 2;
                else
                    addr = bB + (uint32_t)((nb + (tl >> 1) * 8 + rr) * 40
                                           + kk + (tl & 1) * 8) * 2;
                if (BT) LDSM_X4T(bfr[2*np][0], bfr[2*np][1], bfr[2*np+1][0], bfr[2*np+1][1], addr);
                else    LDSM_X4 (bfr[2*np][0], bfr[2*np][1], bfr[2*np+1][0], bfr[2*np+1][1], addr);
            }
            #pragma unroll
            for (int mi = 0; mi < 2; mi++)
                #pragma unroll
                for (int ni = 0; ni < 8; ni++)
                    mma_f16(acc[mi][ni], afr[mi], bfr[ni]);
        }
    }

    if (OM == 1) {
        __half* Cb = (__half*)Cv + (size_t)b * sCb + (size_t)h * sCh;
        #pragma unroll
        for (int mi = 0; mi < 2; mi++) {
            int r0 = m0 + wm + mi * 16 + gid;
            float bv0 = bias ? bias[r0]     : 0.f;
            float bv1 = bias ? bias[r0 + 8] : 0.f;
            #pragma unroll
            for (int ni = 0; ni < 8; ni++) {
                int c0 = n0 + wn + ni * 8 + 2 * tig;
                if (c0 < N) {
                    #pragma unroll
                    for (int j = 0; j < 2; j++) {
                        int c = c0 + j;
                        bool v = (c < nvalid);
                        Cb[(size_t)r0 * ldc + c] =
                            __float2half(v ? alpha * acc[mi][ni][j] + bv0 : 0.f);
                        Cb[(size_t)(r0 + 8) * ldc + c] =
                            __float2half(v ? alpha * acc[mi][ni][2 + j] + bv1 : 0.f);
                    }
                }
            }
        }
    }
}

// ---------------------------------------------------------------- converters
#define N4_VX  (NB * CC * NN / 4)
#define N4_WQ  (CC * CC / 4)
#define N4_WKV (2 * CC * CC / 4)

__global__ void f2h_all(const float* __restrict__ Vx, const float* __restrict__ Wq,
                        const float* __restrict__ Wkv, const float* __restrict__ Wp,
                        __half* __restrict__ dVx, __half* __restrict__ dWq,
                        __half* __restrict__ dWkv, __half* __restrict__ dWp)
{
    int i = blockIdx.x * 256 + threadIdx.x;
    const float* s; __half* d; int j;
    if (i < N4_VX)                       { s = Vx;  d = dVx;  j = i; }
    else if (i < N4_VX + N4_WQ)          { s = Wq;  d = dWq;  j = i - N4_VX; }
    else if (i < N4_VX + N4_WQ + N4_WKV) { s = Wkv; d = dWkv; j = i - N4_VX - N4_WQ; }
    else                                 { s = Wp;  d = dWp;  j = i - N4_VX - N4_WQ - N4_WKV; }
    float4 v = reinterpret_cast<const float4*>(s)[j];
    __half2* d2 = reinterpret_cast<__half2*>(d);
    d2[2 * j]     = __floats2half2_rn(v.x, v.y);
    d2[2 * j + 1] = __floats2half2_rn(v.z, v.w);
}
__global__ void f2h_pad77(const float* __restrict__ s, __half* __restrict__ d, int rows)
{
    int r = blockIdx.x, c = threadIdx.x;
    if (c < TP)
        d[(size_t)r * TP + c] = __float2half((c < TT) ? s[(size_t)r * TT + c] : 0.f);
}

// ---------------------------------------------------------------- launch
extern "C" void kernel_launch(void* const* d_in, const int* in_sizes, int n_in,
                              void* d_out, int out_size)
{
    const float* Vx  = (const float*)d_in[0];
    const float* Tx  = (const float*)d_in[1];
    const float* Wq  = (const float*)d_in[2];
    const float* bq  = (const float*)d_in[3];
    const float* Wkv = (const float*)d_in[4];
    const float* bkv = (const float*)d_in[5];
    const float* Wp  = (const float*)d_in[6];
    const float* bp  = (const float*)d_in[7];
    float* Y = (float*)d_out;

    __half *hVx, *hTx, *hWq, *hWkv, *hWp, *hQ, *hKV, *hO;
    cudaGetSymbolAddress((void**)&hVx, h_Vx);
    cudaGetSymbolAddress((void**)&hTx, h_Tx);
    cudaGetSymbolAddress((void**)&hWq, h_Wq);
    cudaGetSymbolAddress((void**)&hWkv, h_Wkv);
    cudaGetSymbolAddress((void**)&hWp, h_Wp);
    cudaGetSymbolAddress((void**)&hQ,  h_Q);
    cudaGetSymbolAddress((void**)&hKV, h_KV);
    cudaGetSymbolAddress((void**)&hO,  h_O);

    constexpr int SMEM_SMALL = STAGE_B * 3;   // 61440
    cudaFuncSetAttribute(hgemm<false, true, 1>, cudaFuncAttributeMaxDynamicSharedMemorySize, SMEM_SMALL);
    cudaFuncSetAttribute(hgemm_big<1>, cudaFuncAttributeMaxDynamicSharedMemorySize, BIG_SMEM);
    cudaFuncSetAttribute(hgemm_big<0>, cudaFuncAttributeMaxDynamicSharedMemorySize, BIG_SMEM);
    cudaFuncSetAttribute(fused_attn, cudaFuncAttributeMaxDynamicSharedMemorySize, FA_SMEM);

    const float scale = 0.08838834764831843f;  // 1/sqrt(128)

    // 0) fp32 -> fp16
    f2h_all<<<(N4_VX + N4_WQ + N4_WKV + N4_WQ) / 256, 256>>>(
        Vx, Wq, Wkv, Wp, hVx, hWq, hWkv, hWp);
    f2h_pad77<<<NB * CC, 128>>>(Tx, hTx, NB * CC);

    // 1) KV = Wkv @ Tx + bkv : M=2048, N=80(valid 77), K=1024, per-b
    hgemm<false, true, 1><<<dim3(1, 16, NB), 256, SMEM_SMALL>>>(
        hWkv, hTx, hKV, bkv, 2048, TP, CC,
        CC, TP, TP,
        0, 0, (long long)CC * TP, 0,
        (long long)2 * CC * TP, 0, 1, 1.0f, CC, TP, TT);

    // 2) Q = Wq @ Vx + bq : M=1024, N=1024, K=1024, per-b  [BIG BK=128, 2-stage]
    hgemm_big<1><<<dim3(8, 4, NB), 512, BIG_SMEM>>>(
        hWq, hVx, hQ, bq, (long long)CC * NN, (long long)CC * NN);

    // 3) fused attention: S -> register softmax -> O, per (b,h) x n-tile
    fused_attn<<<dim3(8, NB * NH), 256, FA_SMEM>>>(hQ, hKV, hO, scale);

    // 4) Y = Wp @ O + bp : M=1024, N=1024, K=1024, per-b, fp32 out  [BIG BK=128, 2-stage]
    hgemm_big<0><<<dim3(8, 4, NB), 512, BIG_SMEM>>>(
        hWp, hO, Y, bp, (long long)CC * NN, (long long)CC * NN);
}

// round 16
// speedup vs baseline: 1.1305x; 1.1305x over previous
#include <cuda_runtime.h>
#include <cuda_fp16.h>
#include <cstdint>

// ---------------------------------------------------------------------------
// B=16, C=1024, N=1024, T=77(pad 80), heads=8, hd=128.
//   big GEMMs (Q, Y): 128x128x64 tiles, 3 stages, 256 thr, 8 warps,
//     105KB smem -> 2 CTAs/SM (stage-boundary convoys overlap across CTAs)
//   KV: 128x128x32 small GEMM
//   fused attention: S=Q^T K -> register quad-shuffle softmax -> O=V P^T
// Scratch fp16; cols 77..79 stored zero.
// KV head split: K_h rows [256h,256h+128), V_h rows [256h+128,256h+256).
// ---------------------------------------------------------------------------

#define NB 16
#define CC 1024
#define NN 1024
#define TT 77
#define TP 80
#define NH 8
#define HD 128

__device__ __half h_Vx[(size_t)NB * CC * NN];
__device__ __half h_Tx[(size_t)NB * CC * TP];
__device__ __half h_Wq[(size_t)CC * CC];
__device__ __half h_Wkv[(size_t)2 * CC * CC];
__device__ __half h_Wp[(size_t)CC * CC];
__device__ __half h_Q [(size_t)NB * CC * NN];
__device__ __half h_KV[(size_t)NB * 2 * CC * TP];
__device__ __half h_O [(size_t)NB * CC * NN];

__device__ __forceinline__ uint32_t smem_u32(const void* p) {
    uint32_t a;
    asm("{ .reg .u64 t; cvta.to.shared.u64 t, %1; cvt.u32.u64 %0, t; }" : "=r"(a) : "l"(p));
    return a;
}
#define CP16(d, s, sz) asm volatile("cp.async.cg.shared.global [%0], [%1], 16, %2;" :: "r"(d), "l"(s), "r"(sz) : "memory")
#define CP_COMMIT()    asm volatile("cp.async.commit_group;" ::: "memory")
#define CP_WAIT1()     asm volatile("cp.async.wait_group 1;" ::: "memory")
#define CP_WAIT0()     asm volatile("cp.async.wait_group 0;" ::: "memory")

#define LDSM_X4(r0, r1, r2, r3, a) \
    asm volatile("ldmatrix.sync.aligned.m8n8.x4.shared.b16 {%0,%1,%2,%3}, [%4];" \
        : "=r"(r0), "=r"(r1), "=r"(r2), "=r"(r3) : "r"(a))
#define LDSM_X4T(r0, r1, r2, r3, a) \
    asm volatile("ldmatrix.sync.aligned.m8n8.x4.trans.shared.b16 {%0,%1,%2,%3}, [%4];" \
        : "=r"(r0), "=r"(r1), "=r"(r2), "=r"(r3) : "r"(a))

__device__ __forceinline__ void mma_f16(float* c, const uint32_t* a, const uint32_t* b) {
    asm volatile(
        "mma.sync.aligned.m16n8k16.row.col.f32.f16.f16.f32 "
        "{%0,%1,%2,%3}, {%4,%5,%6,%7}, {%8,%9}, {%0,%1,%2,%3};\n"
        : "+f"(c[0]), "+f"(c[1]), "+f"(c[2]), "+f"(c[3])
        : "r"(a[0]), "r"(a[1]), "r"(a[2]), "r"(a[3]), "r"(b[0]), "r"(b[1]));
}

// ===========================================================================
// BIG GEMM: 128x128x64 tiles, 3 stages, 256 thr = 8 warps (4m x 2n),
// warp tile 32x64.  A [m][72]h pitch (144B c-free), B [k][136]h (272B c-free).
// 105KB smem -> 2 CTAs/SM.  OM: 0 = fp32 out, 1 = fp16 out.
// ===========================================================================
#define BIG_A_B 18432                      // 128*72*2
#define BIG_B_B 17408                      // 64*136*2
#define BIG_STAGE (BIG_A_B + BIG_B_B)      // 35840
#define BIG_SMEM (BIG_STAGE * 3)           // 107520

template <int OM>
__global__ __launch_bounds__(256, 2)
void hgemm_big(const __half* __restrict__ A, const __half* __restrict__ B,
               void* __restrict__ Cv, const float* __restrict__ bias,
               long long sBb, long long sCb)
{
    extern __shared__ char smem[];
    const uint32_t sb = smem_u32(smem);

    const int tid  = threadIdx.x;
    const int lane = tid & 31;
    const int warp = tid >> 5;          // 0..7
    const int wm = (warp & 3) * 32;     // 4 warps along M
    const int wn = (warp >> 2) * 64;    // 2 warps along N
    const int gid = lane >> 2;
    const int tig = lane & 3;
    const int tl  = lane >> 3;
    const int rr  = lane & 7;

    const int m0 = blockIdx.y * 128;
    const int n0 = blockIdx.x * 128;
    const __half* Bb = B + (size_t)blockIdx.z * sBb;

    auto load_tile = [&](int kt, int s) {
        const int k0 = kt << 6;
        const uint32_t aB = sb + (uint32_t)s * BIG_STAGE;
        const uint32_t bB = aB + BIG_A_B;
        #pragma unroll
        for (int i = 0; i < 4; i++) {                    // A: 128m x 64k
            int sg = tid + i * 256;
            int m = sg >> 3, seg = sg & 7;
            CP16(aB + (uint32_t)(m * 72 + seg * 8) * 2,
                 A + (size_t)(m0 + m) * CC + k0 + seg * 8, 16);
        }
        #pragma unroll
        for (int i = 0; i < 4; i++) {                    // B: 64k x 128n
            int sg = tid + i * 256;
            int k = sg >> 4, sn = sg & 15;
            CP16(bB + (uint32_t)(k * 136 + sn * 8) * 2,
                 Bb + (size_t)(k0 + k) * NN + n0 + sn * 8, 16);
        }
        CP_COMMIT();
    };

    float acc[2][8][4];
    #pragma unroll
    for (int mi = 0; mi < 2; mi++)
        #pragma unroll
        for (int ni = 0; ni < 8; ni++)
            #pragma unroll
            for (int j = 0; j < 4; j++) acc[mi][ni][j] = 0.f;

    load_tile(0, 0);
    load_tile(1, 1);

    const int nkt = CC >> 6;                 // 16
    for (int kt = 0; kt < nkt; kt++) {
        CP_WAIT1();
        __syncthreads();
        if (kt + 2 < nkt) load_tile(kt + 2, (kt + 2) % 3);
        else CP_COMMIT();

        const uint32_t aB = sb + (uint32_t)((kt % 3) * BIG_STAGE);
        const uint32_t bB = aB + BIG_A_B;

        #pragma unroll
        for (int kk = 0; kk < 64; kk += 16) {
            uint32_t afr[2][4], bfr[8][2];
            #pragma unroll
            for (int mi = 0; mi < 2; mi++) {
                uint32_t addr = aB + (uint32_t)((wm + mi * 16 + (tl & 1) * 8 + rr) * 72
                                                + kk + (tl >> 1) * 8) * 2;
                LDSM_X4(afr[mi][0], afr[mi][1], afr[mi][2], afr[mi][3], addr);
            }
            #pragma unroll
            for (int np = 0; np < 4; np++) {
                uint32_t addr = bB + (uint32_t)((kk + (tl & 1) * 8 + rr) * 136
                                                + wn + np * 16 + (tl >> 1) * 8) * 2;
                LDSM_X4T(bfr[2*np][0], bfr[2*np][1], bfr[2*np+1][0], bfr[2*np+1][1], addr);
            }
            #pragma unroll
            for (int mi = 0; mi < 2; mi++)
                #pragma unroll
                for (int ni = 0; ni < 8; ni++)
                    mma_f16(acc[mi][ni], afr[mi], bfr[ni]);
        }
    }

    #pragma unroll
    for (int mi = 0; mi < 2; mi++) {
        int r0 = m0 + wm + mi * 16 + gid;
        float bv0 = bias[r0];
        float bv1 = bias[r0 + 8];
        #pragma unroll
        for (int ni = 0; ni < 8; ni++) {
            int c0 = n0 + wn + ni * 8 + 2 * tig;
            if (OM == 0) {
                float* Cb = (float*)Cv + (size_t)blockIdx.z * sCb;
                Cb[(size_t)r0 * NN + c0]           = acc[mi][ni][0] + bv0;
                Cb[(size_t)r0 * NN + c0 + 1]       = acc[mi][ni][1] + bv0;
                Cb[(size_t)(r0 + 8) * NN + c0]     = acc[mi][ni][2] + bv1;
                Cb[(size_t)(r0 + 8) * NN + c0 + 1] = acc[mi][ni][3] + bv1;
            } else {
                __half* Cb = (__half*)Cv + (size_t)blockIdx.z * sCb;
                Cb[(size_t)r0 * NN + c0]           = __float2half(acc[mi][ni][0] + bv0);
                Cb[(size_t)r0 * NN + c0 + 1]       = __float2half(acc[mi][ni][1] + bv0);
                Cb[(size_t)(r0 + 8) * NN + c0]     = __float2half(acc[mi][ni][2] + bv1);
                Cb[(size_t)(r0 + 8) * NN + c0 + 1] = __float2half(acc[mi][ni][3] + bv1);
            }
        }
    }
}

// ===========================================================================
// FUSED ATTENTION — unchanged (register quad-shuffle softmax).
// smem: sQ [128d][136]h | sK/sP [128][80]h | sV [128][80]h   = 75776 B
// ===========================================================================
#define FA_SQ 0
#define FA_SK 34816
#define FA_SV 55296
#define FA_SMEM 75776

__global__ __launch_bounds__(256, 2)
void fused_attn(const __half* __restrict__ Q, const __half* __restrict__ KV,
                __half* __restrict__ O, float scale)
{
    extern __shared__ char smem[];
    const uint32_t sb = smem_u32(smem);

    const int tid  = threadIdx.x;
    const int lane = tid & 31;
    const int warp = tid >> 5;
    const int gid = lane >> 2;
    const int tig = lane & 3;
    const int tl  = lane >> 3;
    const int rr  = lane & 7;

    const int n0 = blockIdx.x * 128;
    const int z = blockIdx.y;           // b*8 + h
    const int b = z >> 3, h = z & 7;

    const __half* Qb = Q  + (size_t)b * CC * NN + (size_t)(h * HD) * NN;
    const __half* Kb = KV + (size_t)b * 2 * CC * TP + (size_t)(2 * HD * h) * TP;
    const __half* Vb = Kb + (size_t)HD * TP;

    #pragma unroll
    for (int i = 0; i < 8; i++) {       // Q: 128d x 128n
        int c = tid + i * 256;
        int d = c >> 4, o = (c & 15) * 8;
        CP16(sb + FA_SQ + (uint32_t)(d * 136 + o) * 2,
             Qb + (size_t)d * NN + n0 + o, 16);
    }
    #pragma unroll
    for (int i = 0; i < 5; i++) {       // K: 128d x 80t
        int c = tid + i * 256;
        int d = c / 10, o = (c % 10) * 8;
        CP16(sb + FA_SK + (uint32_t)(d * 80 + o) * 2,
             Kb + (size_t)d * TP + o, 16);
    }
    #pragma unroll
    for (int i = 0; i < 5; i++) {       // V: 128d x 80t
        int c = tid + i * 256;
        int d = c / 10, o = (c % 10) * 8;
        CP16(sb + FA_SV + (uint32_t)(d * 80 + o) * 2,
             Vb + (size_t)d * TP + o, 16);
    }
    CP_COMMIT();
    CP_WAIT0();
    __syncthreads();

    {
        const int wm = warp * 16;
        float accs[10][4];
        #pragma unroll
        for (int ni = 0; ni < 10; ni++)
            #pragma unroll
            for (int j = 0; j < 4; j++) accs[ni][j] = 0.f;

        #pragma unroll
        for (int kk = 0; kk < 128; kk += 16) {
            uint32_t afr[4];
            uint32_t aaddr = sb + FA_SQ + (uint32_t)((kk + (tl >> 1) * 8 + rr) * 136
                                                     + wm + (tl & 1) * 8) * 2;
            LDSM_X4T(afr[0], afr[1], afr[2], afr[3], aaddr);
            uint32_t bfr[10][2];
            #pragma unroll
            for (int tb = 0; tb < 5; tb++) {
                uint32_t baddr = sb + FA_SK + (uint32_t)((kk + (tl & 1) * 8 + rr) * 80
                                                         + tb * 16 + (tl >> 1) * 8) * 2;
                LDSM_X4T(bfr[2*tb][0], bfr[2*tb][1], bfr[2*tb+1][0], bfr[2*tb+1][1], baddr);
            }
            #pragma unroll
            for (int ni = 0; ni < 10; ni++)
                mma_f16(accs[ni], afr, bfr[ni]);
        }

        #pragma unroll
        for (int ni = 0; ni < 10; ni++)
            #pragma unroll
            for (int j = 0; j < 4; j++) accs[ni][j] *= scale;

        float mx0 = -1e30f, mx1 = -1e30f;
        #pragma unroll
        for (int ni = 0; ni < 10; ni++) {
            int c0 = ni * 8 + 2 * tig;
            if (c0 < TT)     { mx0 = fmaxf(mx0, accs[ni][0]); mx1 = fmaxf(mx1, accs[ni][2]); }
            if (c0 + 1 < TT) { mx0 = fmaxf(mx0, accs[ni][1]); mx1 = fmaxf(mx1, accs[ni][3]); }
        }
        mx0 = fmaxf(mx0, __shfl_xor_sync(0xFFFFFFFFu, mx0, 1));
        mx0 = fmaxf(mx0, __shfl_xor_sync(0xFFFFFFFFu, mx0, 2));
        mx1 = fmaxf(mx1, __shfl_xor_sync(0xFFFFFFFFu, mx1, 1));
        mx1 = fmaxf(mx1, __shfl_xor_sync(0xFFFFFFFFu, mx1, 2));

        float s0 = 0.f, s1 = 0.f;
        #pragma unroll
        for (int ni = 0; ni < 10; ni++) {
            int c0 = ni * 8 + 2 * tig;
            float e0 = (c0 < TT)     ? __expf(accs[ni][0] - mx0) : 0.f;
            float e1 = (c0 + 1 < TT) ? __expf(accs[ni][1] - mx0) : 0.f;
            float e2 = (c0 < TT)     ? __expf(accs[ni][2] - mx1) : 0.f;
            float e3 = (c0 + 1 < TT) ? __expf(accs[ni][3] - mx1) : 0.f;
            accs[ni][0] = e0; accs[ni][1] = e1; accs[ni][2] = e2; accs[ni][3] = e3;
            s0 += e0 + e1; s1 += e2 + e3;
        }
        s0 += __shfl_xor_sync(0xFFFFFFFFu, s0, 1);
        s0 += __shfl_xor_sync(0xFFFFFFFFu, s0, 2);
        s1 += __shfl_xor_sync(0xFFFFFFFFu, s1, 1);
        s1 += __shfl_xor_sync(0xFFFFFFFFu, s1, 2);
        float inv0 = 1.f / s0, inv1 = 1.f / s1;

        __syncthreads();

        __half* P = (__half*)(smem + FA_SK);
        #pragma unroll
        for (int ni = 0; ni < 10; ni++) {
            int c0 = ni * 8 + 2 * tig;
            *reinterpret_cast<__half2*>(P + (wm + gid) * 80 + c0) =
                __floats2half2_rn(accs[ni][0] * inv0, accs[ni][1] * inv0);
            *reinterpret_cast<__half2*>(P + (wm + gid + 8) * 80 + c0) =
                __floats2half2_rn(accs[ni][2] * inv1, accs[ni][3] * inv1);
        }
    }
    __syncthreads();

    {
        const int wm2 = (warp & 3) * 32;
        const int wn2 = (warp >> 2) * 64;
        float acco[2][8][4];
        #pragma unroll
        for (int mi = 0; mi < 2; mi++)
            #pragma unroll
            for (int ni = 0; ni < 8; ni++)
                #pragma unroll
                for (int j = 0; j < 4; j++) acco[mi][ni][j] = 0.f;

        #pragma unroll
        for (int kk = 0; kk < 80; kk += 16) {
            uint32_t afr[2][4], bfr[8][2];
            #pragma unroll
            for (int mi = 0; mi < 2; mi++) {
                uint32_t addr = sb + FA_SV + (uint32_t)((wm2 + mi * 16 + (tl & 1) * 8 + rr) * 80
                                                        + kk + (tl >> 1) * 8) * 2;
                LDSM_X4(afr[mi][0], afr[mi][1], afr[mi][2], afr[mi][3], addr);
            }
            #pragma unroll
            for (int np = 0; np < 4; np++) {
                uint32_t addr = sb + FA_SK + (uint32_t)((wn2 + np * 16 + (tl >> 1) * 8 + rr) * 80
                                                        + kk + (tl & 1) * 8) * 2;
                LDSM_X4(bfr[2*np][0], bfr[2*np][1], bfr[2*np+1][0], bfr[2*np+1][1], addr);
            }
            #pragma unroll
            for (int mi = 0; mi < 2; mi++)
                #pragma unroll
                for (int ni = 0; ni < 8; ni++)
                    mma_f16(acco[mi][ni], afr[mi], bfr[ni]);
        }

        __half* Ob = O + (size_t)b * CC * NN + (size_t)(h * HD) * NN;
        #pragma unroll
        for (int mi = 0; mi < 2; mi++) {
            int r0 = wm2 + mi * 16 + gid;
            #pragma unroll
            for (int ni = 0; ni < 8; ni++) {
                int c0 = n0 + wn2 + ni * 8 + 2 * tig;
                Ob[(size_t)r0 * NN + c0]           = __float2half(acco[mi][ni][0]);
                Ob[(size_t)r0 * NN + c0 + 1]       = __float2half(acco[mi][ni][1]);
                Ob[(size_t)(r0 + 8) * NN + c0]     = __float2half(acco[mi][ni][2]);
                Ob[(size_t)(r0 + 8) * NN + c0 + 1] = __float2half(acco[mi][ni][3]);
            }
        }
    }
}

// ===========================================================================
// Small generic GEMM — KV projection only (unchanged).
// ===========================================================================
#define STAGE_B 20480

template <bool AT, bool BT, int OM>
__global__ __launch_bounds__(256, 2)
void hgemm(const __half* __restrict__ A, const __half* __restrict__ B,
           void* __restrict__ Cv, const float* __restrict__ bias,
           int M, int N, int K,
           long long sA, long long sB, long long ldc,
           long long sAb, long long sAh, long long sBb, long long sBh,
           long long sCb, long long sCh, int nh, float alpha,
           int Ka, int Bbound, int nvalid)
{
    extern __shared__ char smem[];
    const uint32_t sb = smem_u32(smem);

    const int tid  = threadIdx.x;
    const int lane = tid & 31;
    const int warp = tid >> 5;
    const int wm = (warp & 3) * 32;
    const int wn = (warp >> 2) * 64;
    const int gid = lane >> 2;
    const int tig = lane & 3;
    const int tl  = lane >> 3;
    const int rr  = lane & 7;

    const int z = blockIdx.z;
    const int b = z / nh;
    const int h = z - b * nh;
    const __half* Ab = A + (size_t)b * sAb + (size_t)h * sAh;
    const __half* Bb = B + (size_t)b * sBb + (size_t)h * sBh;

    const int m0 = blockIdx.y * 128;
    const int n0 = blockIdx.x * 128;
    const int nkt = (K + 31) >> 5;

    auto load_tile = [&](int kt, int s) {
        const int k0 = kt << 5;
        const uint32_t aB = sb + (uint32_t)s * STAGE_B;
        const uint32_t bB = aB + 10240;
        #pragma unroll
        for (int i = 0; i < 2; i++) {
            int sg = tid + i * 256;
            if (!AT) {
                int m = sg >> 2, sk = sg & 3;
                CP16(aB + (uint32_t)(m * 40 + sk * 8) * 2,
                     Ab + (size_t)(m0 + m) * sA + k0 + sk * 8,
                     (k0 + sk * 8 < Ka) ? 16 : 0);
            } else {
                int k = sg >> 4, sm = sg & 15;
                CP16(aB + (uint32_t)(k * 136 + sm * 8) * 2,
                     Ab + (size_t)(k0 + k) * sA + m0 + sm * 8, 16);
            }
        }
        #pragma unroll
        for (int i = 0; i < 2; i++) {
            int sg = tid + i * 256;
            if (BT) {
                int k = sg >> 4, sn = sg & 15;
                CP16(bB + (uint32_t)(k * 136 + sn * 8) * 2,
                     Bb + (size_t)(k0 + k) * sB + n0 + sn * 8,
                     (n0 + sn * 8 < Bbound) ? 16 : 0);
            } else {
                int n = sg >> 2, sk = sg & 3;
                CP16(bB + (uint32_t)(n * 40 + sk * 8) * 2,
                     Bb + (size_t)(n0 + n) * sB + k0 + sk * 8,
                     (k0 + sk * 8 < Bbound) ? 16 : 0);
            }
        }
        CP_COMMIT();
    };

    float acc[2][8][4];
    #pragma unroll
    for (int mi = 0; mi < 2; mi++)
        #pragma unroll
        for (int ni = 0; ni < 8; ni++)
            #pragma unroll
            for (int j = 0; j < 4; j++) acc[mi][ni][j] = 0.f;

    load_tile(0, 0);
    if (nkt > 1) load_tile(1, 1); else CP_COMMIT();

    for (int kt = 0; kt < nkt; kt++) {
        CP_WAIT1();
        __syncthreads();
        if (kt + 2 < nkt) load_tile(kt + 2, (kt + 2) % 3);
        else CP_COMMIT();

        const uint32_t aB = sb + (uint32_t)((kt % 3) * STAGE_B);
        const uint32_t bB = aB + 10240;

        #pragma unroll
        for (int kk = 0; kk < 32; kk += 16) {
            uint32_t afr[2][4], bfr[8][2];
            #pragma unroll
            for (int mi = 0; mi < 2; mi++) {
                uint32_t addr;
                if (!AT)
                    addr = aB + (uint32_t)((wm + mi * 16 + (tl & 1) * 8 + rr) * 40
                                           + kk + (tl >> 1) * 8) * 2;
                else
                    addr = aB + (uint32_t)((kk + (tl >> 1) * 8 + rr) * 136
                                           + wm + mi * 16 + (tl & 1) * 8) * 2;
                if (!AT) LDSM_X4 (afr[mi][0], afr[mi][1], afr[mi][2], afr[mi][3], addr);
                else     LDSM_X4T(afr[mi][0], afr[mi][1], afr[mi][2], afr[mi][3], addr);
            }
            #pragma unroll
            for (int np = 0; np < 4; np++) {
                int nb = wn + np * 16;
                uint32_t addr;
                if (BT)
                    addr = bB + (uint32_t)((kk + (tl & 1) * 8 + rr) * 136
                                           + nb + (tl >> 1) * 8) * 2;
                else
                    addr = bB + (uint32_t)((nb + (tl >> 1) * 8 + rr) * 40
                                           + kk + (tl & 1) * 8) * 2;
                if (BT) LDSM_X4T(bfr[2*np][0], bfr[2*np][1], bfr[2*np+1][0], bfr[2*np+1][1], addr);
                else    LDSM_X4 (bfr[2*np][0], bfr[2*np][1], bfr[2*np+1][0], bfr[2*np+1][1], addr);
            }
            #pragma unroll
            for (int mi = 0; mi < 2; mi++)
                #pragma unroll
                for (int ni = 0; ni < 8; ni++)
                    mma_f16(acc[mi][ni], afr[mi], bfr[ni]);
        }
    }

    if (OM == 1) {
        __half* Cb = (__half*)Cv + (size_t)b * sCb + (size_t)h * sCh;
        #pragma unroll
        for (int mi = 0; mi < 2; mi++) {
            int r0 = m0 + wm + mi * 16 + gid;
            float bv0 = bias ? bias[r0]     : 0.f;
            float bv1 = bias ? bias[r0 + 8] : 0.f;
            #pragma unroll
            for (int ni = 0; ni < 8; ni++) {
                int c0 = n0 + wn + ni * 8 + 2 * tig;
                if (c0 < N) {
                    #pragma unroll
                    for (int j = 0; j < 2; j++) {
                        int c = c0 + j;
                        bool v = (c < nvalid);
                        Cb[(size_t)r0 * ldc + c] =
                            __float2half(v ? alpha * acc[mi][ni][j] + bv0 : 0.f);
                        Cb[(size_t)(r0 + 8) * ldc + c] =
                            __float2half(v ? alpha * acc[mi][ni][2 + j] + bv1 : 0.f);
                    }
                }
            }
        }
    }
}

// ---------------------------------------------------------------- converters
#define N4_VX  (NB * CC * NN / 4)
#define N4_WQ  (CC * CC / 4)
#define N4_WKV (2 * CC * CC / 4)

__global__ void f2h_all(const float* __restrict__ Vx, const float* __restrict__ Wq,
                        const float* __restrict__ Wkv, const float* __restrict__ Wp,
                        __half* __restrict__ dVx, __half* __restrict__ dWq,
                        __half* __restrict__ dWkv, __half* __restrict__ dWp)
{
    int i = blockIdx.x * 256 + threadIdx.x;
    const float* s; __half* d; int j;
    if (i < N4_VX)                       { s = Vx;  d = dVx;  j = i; }
    else if (i < N4_VX + N4_WQ)          { s = Wq;  d = dWq;  j = i - N4_VX; }
    else if (i < N4_VX + N4_WQ + N4_WKV) { s = Wkv; d = dWkv; j = i - N4_VX - N4_WQ; }
    else                                 { s = Wp;  d = dWp;  j = i - N4_VX - N4_WQ - N4_WKV; }
    float4 v = reinterpret_cast<const float4*>(s)[j];
    __half2* d2 = reinterpret_cast<__half2*>(d);
    d2[2 * j]     = __floats2half2_rn(v.x, v.y);
    d2[2 * j + 1] = __floats2half2_rn(v.z, v.w);
}
__global__ void f2h_pad77(const float* __restrict__ s, __half* __restrict__ d, int rows)
{
    int r = blockIdx.x, c = threadIdx.x;
    if (c < TP)
        d[(size_t)r * TP + c] = __float2half((c < TT) ? s[(size_t)r * TT + c] : 0.f);
}

// ---------------------------------------------------------------- launch
extern "C" void kernel_launch(void* const* d_in, const int* in_sizes, int n_in,
                              void* d_out, int out_size)
{
    const float* Vx  = (const float*)d_in[0];
    const float* Tx  = (const float*)d_in[1];
    const float* Wq  = (const float*)d_in[2];
    const float* bq  = (const float*)d_in[3];
    const float* Wkv = (const float*)d_in[4];
    const float* bkv = (const float*)d_in[5];
    const float* Wp  = (const float*)d_in[6];
    const float* bp  = (const float*)d_in[7];
    float* Y = (float*)d_out;

    __half *hVx, *hTx, *hWq, *hWkv, *hWp, *hQ, *hKV, *hO;
    cudaGetSymbolAddress((void**)&hVx, h_Vx);
    cudaGetSymbolAddress((void**)&hTx, h_Tx);
    cudaGetSymbolAddress((void**)&hWq, h_Wq);
    cudaGetSymbolAddress((void**)&hWkv, h_Wkv);
    cudaGetSymbolAddress((void**)&hWp, h_Wp);
    cudaGetSymbolAddress((void**)&hQ,  h_Q);
    cudaGetSymbolAddress((void**)&hKV, h_KV);
    cudaGetSymbolAddress((void**)&hO,  h_O);

    constexpr int SMEM_SMALL = STAGE_B * 3;   // 61440
    cudaFuncSetAttribute(hgemm<false, true, 1>, cudaFuncAttributeMaxDynamicSharedMemorySize, SMEM_SMALL);
    cudaFuncSetAttribute(hgemm_big<1>, cudaFuncAttributeMaxDynamicSharedMemorySize, BIG_SMEM);
    cudaFuncSetAttribute(hgemm_big<0>, cudaFuncAttributeMaxDynamicSharedMemorySize, BIG_SMEM);
    cudaFuncSetAttribute(fused_attn, cudaFuncAttributeMaxDynamicSharedMemorySize, FA_SMEM);

    const float scale = 0.08838834764831843f;  // 1/sqrt(128)

    // 0) fp32 -> fp16
    f2h_all<<<(N4_VX + N4_WQ + N4_WKV + N4_WQ) / 256, 256>>>(
        Vx, Wq, Wkv, Wp, hVx, hWq, hWkv, hWp);
    f2h_pad77<<<NB * CC, 128>>>(Tx, hTx, NB * CC);

    // 1) KV = Wkv @ Tx + bkv : M=2048, N=80(valid 77), K=1024, per-b
    hgemm<false, true, 1><<<dim3(1, 16, NB), 256, SMEM_SMALL>>>(
        hWkv, hTx, hKV, bkv, 2048, TP, CC,
        CC, TP, TP,
        0, 0, (long long)CC * TP, 0,
        (long long)2 * CC * TP, 0, 1, 1.0f, CC, TP, TT);

    // 2) Q = Wq @ Vx + bq : M=1024, N=1024, K=1024, per-b  [BIG 128x128x64, 2 CTA/SM]
    hgemm_big<1><<<dim3(8, 8, NB), 256, BIG_SMEM>>>(
        hWq, hVx, hQ, bq, (long long)CC * NN, (long long)CC * NN);

    // 3) fused attention: S -> register softmax -> O, per (b,h) x n-tile
    fused_attn<<<dim3(8, NB * NH), 256, FA_SMEM>>>(hQ, hKV, hO, scale);

    // 4) Y = Wp @ O + bp : M=1024, N=1024, K=1024, per-b, fp32 out  [BIG 2 CTA/SM]
    hgemm_big<0><<<dim3(8, 8, NB), 256, BIG_SMEM>>>(
        hWp, hO, Y, bp, (long long)CC * NN, (long long)CC * NN);
}

// round 17
// speedup vs baseline: 1.2417x; 1.0983x over previous
#include <cuda_runtime.h>
#include <cuda_fp16.h>
#include <cstdint>

// ---------------------------------------------------------------------------
// B=16, C=1024, N=1024, T=77(pad 80), heads=8, hd=128.
//   KV: 128x128x32 small GEMM
//   fused_qattn: Q-proj (128x128x1024, round-16 mainloop) -> Q in smem ->
//                S=Q^T K -> register quad-shuffle softmax -> O=V P^T
//                (Q never touches HBM; K/V prefetch overlaps Q epilogue)
//   Y: 128x128x64 big GEMM, 3 stages, 2 CTAs/SM (round-16 config)
// Scratch fp16; cols 77..79 stored zero.
// KV head split: K_h rows [256h,256h+128), V_h rows [256h+128,256h+256).
// ---------------------------------------------------------------------------

#define NB 16
#define CC 1024
#define NN 1024
#define TT 77
#define TP 80
#define NH 8
#define HD 128

__device__ __half h_Vx[(size_t)NB * CC * NN];
__device__ __half h_Tx[(size_t)NB * CC * TP];
__device__ __half h_Wq[(size_t)CC * CC];
__device__ __half h_Wkv[(size_t)2 * CC * CC];
__device__ __half h_Wp[(size_t)CC * CC];
__device__ __half h_KV[(size_t)NB * 2 * CC * TP];
__device__ __half h_O [(size_t)NB * CC * NN];

__device__ __forceinline__ uint32_t smem_u32(const void* p) {
    uint32_t a;
    asm("{ .reg .u64 t; cvta.to.shared.u64 t, %1; cvt.u32.u64 %0, t; }" : "=r"(a) : "l"(p));
    return a;
}
#define CP16(d, s, sz) asm volatile("cp.async.cg.shared.global [%0], [%1], 16, %2;" :: "r"(d), "l"(s), "r"(sz) : "memory")
#define CP_COMMIT()    asm volatile("cp.async.commit_group;" ::: "memory")
#define CP_WAIT1()     asm volatile("cp.async.wait_group 1;" ::: "memory")
#define CP_WAIT0()     asm volatile("cp.async.wait_group 0;" ::: "memory")

#define LDSM_X4(r0, r1, r2, r3, a) \
    asm volatile("ldmatrix.sync.aligned.m8n8.x4.shared.b16 {%0,%1,%2,%3}, [%4];" \
        : "=r"(r0), "=r"(r1), "=r"(r2), "=r"(r3) : "r"(a))
#define LDSM_X4T(r0, r1, r2, r3, a) \
    asm volatile("ldmatrix.sync.aligned.m8n8.x4.trans.shared.b16 {%0,%1,%2,%3}, [%4];" \
        : "=r"(r0), "=r"(r1), "=r"(r2), "=r"(r3) : "r"(a))

__device__ __forceinline__ void mma_f16(float* c, const uint32_t* a, const uint32_t* b) {
    asm volatile(
        "mma.sync.aligned.m16n8k16.row.col.f32.f16.f16.f32 "
        "{%0,%1,%2,%3}, {%4,%5,%6,%7}, {%8,%9}, {%0,%1,%2,%3};\n"
        : "+f"(c[0]), "+f"(c[1]), "+f"(c[2]), "+f"(c[3])
        : "r"(a[0]), "r"(a[1]), "r"(a[2]), "r"(a[3]), "r"(b[0]), "r"(b[1]));
}

// Shared tiling constants (128x128x64 mainloop, 3 stages, 8 warps 4m x 2n)
#define BIG_A_B 18432                      // 128*72*2
#define BIG_B_B 17408                      // 64*136*2
#define BIG_STAGE (BIG_A_B + BIG_B_B)      // 35840
#define BIG_SMEM (BIG_STAGE * 3)           // 107520

// ===========================================================================
// BIG GEMM (Y projection): identical to round 16, OM=0 fp32 out.
// ===========================================================================
template <int OM>
__global__ __launch_bounds__(256, 2)
void hgemm_big(const __half* __restrict__ A, const __half* __restrict__ B,
               void* __restrict__ Cv, const float* __restrict__ bias,
               long long sBb, long long sCb)
{
    extern __shared__ char smem[];
    const uint32_t sb = smem_u32(smem);

    const int tid  = threadIdx.x;
    const int lane = tid & 31;
    const int warp = tid >> 5;
    const int wm = (warp & 3) * 32;
    const int wn = (warp >> 2) * 64;
    const int gid = lane >> 2;
    const int tig = lane & 3;
    const int tl  = lane >> 3;
    const int rr  = lane & 7;

    const int m0 = blockIdx.y * 128;
    const int n0 = blockIdx.x * 128;
    const __half* Bb = B + (size_t)blockIdx.z * sBb;

    auto load_tile = [&](int kt, int s) {
        const int k0 = kt << 6;
        const uint32_t aB = sb + (uint32_t)s * BIG_STAGE;
        const uint32_t bB = aB + BIG_A_B;
        #pragma unroll
        for (int i = 0; i < 4; i++) {
            int sg = tid + i * 256;
            int m = sg >> 3, seg = sg & 7;
            CP16(aB + (uint32_t)(m * 72 + seg * 8) * 2,
                 A + (size_t)(m0 + m) * CC + k0 + seg * 8, 16);
        }
        #pragma unroll
        for (int i = 0; i < 4; i++) {
            int sg = tid + i * 256;
            int k = sg >> 4, sn = sg & 15;
            CP16(bB + (uint32_t)(k * 136 + sn * 8) * 2,
                 Bb + (size_t)(k0 + k) * NN + n0 + sn * 8, 16);
        }
        CP_COMMIT();
    };

    float acc[2][8][4];
    #pragma unroll
    for (int mi = 0; mi < 2; mi++)
        #pragma unroll
        for (int ni = 0; ni < 8; ni++)
            #pragma unroll
            for (int j = 0; j < 4; j++) acc[mi][ni][j] = 0.f;

    load_tile(0, 0);
    load_tile(1, 1);

    const int nkt = CC >> 6;
    for (int kt = 0; kt < nkt; kt++) {
        CP_WAIT1();
        __syncthreads();
        if (kt + 2 < nkt) load_tile(kt + 2, (kt + 2) % 3);
        else CP_COMMIT();

        const uint32_t aB = sb + (uint32_t)((kt % 3) * BIG_STAGE);
        const uint32_t bB = aB + BIG_A_B;

        #pragma unroll
        for (int kk = 0; kk < 64; kk += 16) {
            uint32_t afr[2][4], bfr[8][2];
            #pragma unroll
            for (int mi = 0; mi < 2; mi++) {
                uint32_t addr = aB + (uint32_t)((wm + mi * 16 + (tl & 1) * 8 + rr) * 72
                                                + kk + (tl >> 1) * 8) * 2;
                LDSM_X4(afr[mi][0], afr[mi][1], afr[mi][2], afr[mi][3], addr);
            }
            #pragma unroll
            for (int np = 0; np < 4; np++) {
                uint32_t addr = bB + (uint32_t)((kk + (tl & 1) * 8 + rr) * 136
                                                + wn + np * 16 + (tl >> 1) * 8) * 2;
                LDSM_X4T(bfr[2*np][0], bfr[2*np][1], bfr[2*np+1][0], bfr[2*np+1][1], addr);
            }
            #pragma unroll
            for (int mi = 0; mi < 2; mi++)
                #pragma unroll
                for (int ni = 0; ni < 8; ni++)
                    mma_f16(acc[mi][ni], afr[mi], bfr[ni]);
        }
    }

    #pragma unroll
    for (int mi = 0; mi < 2; mi++) {
        int r0 = m0 + wm + mi * 16 + gid;
        float bv0 = bias[r0];
        float bv1 = bias[r0 + 8];
        #pragma unroll
        for (int ni = 0; ni < 8; ni++) {
            int c0 = n0 + wn + ni * 8 + 2 * tig;
            if (OM == 0) {
                float* Cb = (float*)Cv + (size_t)blockIdx.z * sCb;
                Cb[(size_t)r0 * NN + c0]           = acc[mi][ni][0] + bv0;
                Cb[(size_t)r0 * NN + c0 + 1]       = acc[mi][ni][1] + bv0;
                Cb[(size_t)(r0 + 8) * NN + c0]     = acc[mi][ni][2] + bv1;
                Cb[(size_t)(r0 + 8) * NN + c0 + 1] = acc[mi][ni][3] + bv1;
            } else {
                __half* Cb = (__half*)Cv + (size_t)blockIdx.z * sCb;
                Cb[(size_t)r0 * NN + c0]           = __float2half(acc[mi][ni][0] + bv0);
                Cb[(size_t)r0 * NN + c0 + 1]       = __float2half(acc[mi][ni][1] + bv0);
                Cb[(size_t)(r0 + 8) * NN + c0]     = __float2half(acc[mi][ni][2] + bv1);
                Cb[(size_t)(r0 + 8) * NN + c0 + 1] = __float2half(acc[mi][ni][3] + bv1);
            }
        }
    }
}

// ===========================================================================
// FUSED Q-PROJECTION + ATTENTION.  Grid (8 ntiles, 8 h, 16 b), 256 thr.
//   Phase 1: Q-tile = Wq[h*128..+128, :] @ Vx[b][:, n0..+128] + bq
//            (round-16 mainloop; acc in regs)
//   Phase 2: acc -> sQ (fp16, stage0 smem); K/V cp.async into stage1/2
//            overlapping the register->smem writes.
//   Phase 3: S = Q^T K, register quad-shuffle softmax, P -> sK region,
//            O = V P^T -> gmem.
// smem: stage0 = sQ [128][136]h (34816<=35840), stage1 = sK/sP [128][80]h,
//       stage2 = sV [128][80]h.  Total 107520 -> 2 CTAs/SM.
// ===========================================================================
#define FQ_SQ 0
#define FQ_SK BIG_STAGE
#define FQ_SV (BIG_STAGE * 2)

__global__ __launch_bounds__(256, 2)
void fused_qattn(const __half* __restrict__ Wq, const __half* __restrict__ Vx,
                 const float* __restrict__ bq, const __half* __restrict__ KV,
                 __half* __restrict__ O, float scale)
{
    extern __shared__ char smem[];
    const uint32_t sb = smem_u32(smem);

    const int tid  = threadIdx.x;
    const int lane = tid & 31;
    const int warp = tid >> 5;
    const int wm = (warp & 3) * 32;
    const int wn = (warp >> 2) * 64;
    const int gid = lane >> 2;
    const int tig = lane & 3;
    const int tl  = lane >> 3;
    const int rr  = lane & 7;

    const int n0 = blockIdx.x * 128;
    const int h  = blockIdx.y;
    const int b  = blockIdx.z;
    const int m0 = h * HD;                    // Wq row block = head's d rows

    const __half* Bb = Vx + (size_t)b * CC * NN;
    const __half* Kb = KV + (size_t)b * 2 * CC * TP + (size_t)(2 * HD * h) * TP;
    const __half* Vb = Kb + (size_t)HD * TP;

    // ---------------- Phase 1: Q-tile GEMM (128x128x1024) ----------------
    auto load_tile = [&](int kt, int s) {
        const int k0 = kt << 6;
        const uint32_t aB = sb + (uint32_t)s * BIG_STAGE;
        const uint32_t bB = aB + BIG_A_B;
        #pragma unroll
        for (int i = 0; i < 4; i++) {
            int sg = tid + i * 256;
            int m = sg >> 3, seg = sg & 7;
            CP16(aB + (uint32_t)(m * 72 + seg * 8) * 2,
                 Wq + (size_t)(m0 + m) * CC + k0 + seg * 8, 16);
        }
        #pragma unroll
        for (int i = 0; i < 4; i++) {
            int sg = tid + i * 256;
            int k = sg >> 4, sn = sg & 15;
            CP16(bB + (uint32_t)(k * 136 + sn * 8) * 2,
                 Bb + (size_t)(k0 + k) * NN + n0 + sn * 8, 16);
        }
        CP_COMMIT();
    };

    float acc[2][8][4];
    #pragma unroll
    for (int mi = 0; mi < 2; mi++)
        #pragma unroll
        for (int ni = 0; ni < 8; ni++)
            #pragma unroll
            for (int j = 0; j < 4; j++) acc[mi][ni][j] = 0.f;

    load_tile(0, 0);
    load_tile(1, 1);

    const int nkt = CC >> 6;                  // 16
    for (int kt = 0; kt < nkt; kt++) {
        CP_WAIT1();
        __syncthreads();
        if (kt + 2 < nkt) load_tile(kt + 2, (kt + 2) % 3);
        else CP_COMMIT();

        const uint32_t aB = sb + (uint32_t)((kt % 3) * BIG_STAGE);
        const uint32_t bB = aB + BIG_A_B;

        #pragma unroll
        for (int kk = 0; kk < 64; kk += 16) {
            uint32_t afr[2][4], bfr[8][2];
            #pragma unroll
            for (int mi = 0; mi < 2; mi++) {
                uint32_t addr = aB + (uint32_t)((wm + mi * 16 + (tl & 1) * 8 + rr) * 72
                                                + kk + (tl >> 1) * 8) * 2;
                LDSM_X4(afr[mi][0], afr[mi][1], afr[mi][2], afr[mi][3], addr);
            }
            #pragma unroll
            for (int np = 0; np < 4; np++) {
                uint32_t addr = bB + (uint32_t)((kk + (tl & 1) * 8 + rr) * 136
                                                + wn + np * 16 + (tl >> 1) * 8) * 2;
                LDSM_X4T(bfr[2*np][0], bfr[2*np][1], bfr[2*np+1][0], bfr[2*np+1][1], addr);
            }
            #pragma unroll
            for (int mi = 0; mi < 2; mi++)
                #pragma unroll
                for (int ni = 0; ni < 8; ni++)
                    mma_f16(acc[mi][ni], afr[mi], bfr[ni]);
        }
    }
    CP_WAIT0();
    __syncthreads();                          // all MMA smem reads complete

    // ---------------- Phase 2: K/V prefetch + Q -> smem ----------------
    #pragma unroll
    for (int i = 0; i < 5; i++) {             // K: 128d x 80t -> stage1
        int c = tid + i * 256;
        int d = c / 10, o = (c % 10) * 8;
        CP16(sb + FQ_SK + (uint32_t)(d * 80 + o) * 2,
             Kb + (size_t)d * TP + o, 16);
    }
    #pragma unroll
    for (int i = 0; i < 5; i++) {             // V: 128d x 80t -> stage2
        int c = tid + i * 256;
        int d = c / 10, o = (c % 10) * 8;
        CP16(sb + FQ_SV + (uint32_t)(d * 80 + o) * 2,
             Vb + (size_t)d * TP + o, 16);
    }
    CP_COMMIT();

    {   // write Q (fp16, + bias) into sQ [d][136] while K/V fly
        __half* sQ = (__half*)smem;           // stage0
        #pragma unroll
        for (int mi = 0; mi < 2; mi++) {
            int r0 = wm + mi * 16 + gid;      // local d row
            float bv0 = bq[m0 + r0];
            float bv1 = bq[m0 + r0 + 8];
            #pragma unroll
            for (int ni = 0; ni < 8; ni++) {
                int c0 = wn + ni * 8 + 2 * tig;   // local n col
                *reinterpret_cast<__half2*>(sQ + r0 * 136 + c0) =
                    __floats2half2_rn(acc[mi][ni][0] + bv0, acc[mi][ni][1] + bv0);
                *reinterpret_cast<__half2*>(sQ + (r0 + 8) * 136 + c0) =
                    __floats2half2_rn(acc[mi][ni][2] + bv1, acc[mi][ni][3] + bv1);
            }
        }
    }
    CP_WAIT0();
    __syncthreads();

    // ---------------- Phase 3: S = Q^T K, softmax, O = V P^T ----------------
    {
        const int wms = warp * 16;            // warp owns 16 n-rows
        float accs[10][4];
        #pragma unroll
        for (int ni = 0; ni < 10; ni++)
            #pragma unroll
            for (int j = 0; j < 4; j++) accs[ni][j] = 0.f;

        #pragma unroll
        for (int kk = 0; kk < 128; kk += 16) {
            uint32_t afr[4];
            uint32_t aaddr = sb + FQ_SQ + (uint32_t)((kk + (tl >> 1) * 8 + rr) * 136
                                                     + wms + (tl & 1) * 8) * 2;
            LDSM_X4T(afr[0], afr[1], afr[2], afr[3], aaddr);
            uint32_t bfr[10][2];
            #pragma unroll
            for (int tb = 0; tb < 5; tb++) {
                uint32_t baddr = sb + FQ_SK + (uint32_t)((kk + (tl & 1) * 8 + rr) * 80
                                                         + tb * 16 + (tl >> 1) * 8) * 2;
                LDSM_X4T(bfr[2*tb][0], bfr[2*tb][1], bfr[2*tb+1][0], bfr[2*tb+1][1], baddr);
            }
            #pragma unroll
            for (int ni = 0; ni < 10; ni++)
                mma_f16(accs[ni], afr, bfr[ni]);
        }

        #pragma unroll
        for (int ni = 0; ni < 10; ni++)
            #pragma unroll
            for (int j = 0; j < 4; j++) accs[ni][j] *= scale;

        float mx0 = -1e30f, mx1 = -1e30f;
        #pragma unroll
        for (int ni = 0; ni < 10; ni++) {
            int c0 = ni * 8 + 2 * tig;
            if (c0 < TT)     { mx0 = fmaxf(mx0, accs[ni][0]); mx1 = fmaxf(mx1, accs[ni][2]); }
            if (c0 + 1 < TT) { mx0 = fmaxf(mx0, accs[ni][1]); mx1 = fmaxf(mx1, accs[ni][3]); }
        }
        mx0 = fmaxf(mx0, __shfl_xor_sync(0xFFFFFFFFu, mx0, 1));
        mx0 = fmaxf(mx0, __shfl_xor_sync(0xFFFFFFFFu, mx0, 2));
        mx1 = fmaxf(mx1, __shfl_xor_sync(0xFFFFFFFFu, mx1, 1));
        mx1 = fmaxf(mx1, __shfl_xor_sync(0xFFFFFFFFu, mx1, 2));

        float s0 = 0.f, s1 = 0.f;
        #pragma unroll
        for (int ni = 0; ni < 10; ni++) {
            int c0 = ni * 8 + 2 * tig;
            float e0 = (c0 < TT)     ? __expf(accs[ni][0] - mx0) : 0.f;
            float e1 = (c0 + 1 < TT) ? __expf(accs[ni][1] - mx0) : 0.f;
            float e2 = (c0 < TT)     ? __expf(accs[ni][2] - mx1) : 0.f;
            float e3 = (c0 + 1 < TT) ? __expf(accs[ni][3] - mx1) : 0.f;
            accs[ni][0] = e0; accs[ni][1] = e1; accs[ni][2] = e2; accs[ni][3] = e3;
            s0 += e0 + e1; s1 += e2 + e3;
        }
        s0 += __shfl_xor_sync(0xFFFFFFFFu, s0, 1);
        s0 += __shfl_xor_sync(0xFFFFFFFFu, s0, 2);
        s1 += __shfl_xor_sync(0xFFFFFFFFu, s1, 1);
        s1 += __shfl_xor_sync(0xFFFFFFFFu, s1, 2);
        float inv0 = 1.f / s0, inv1 = 1.f / s1;

        __syncthreads();                      // all warps done reading sK as K

        __half* P = (__half*)(smem + FQ_SK);
        #pragma unroll
        for (int ni = 0; ni < 10; ni++) {
            int c0 = ni * 8 + 2 * tig;
            *reinterpret_cast<__half2*>(P + (wms + gid) * 80 + c0) =
                __floats2half2_rn(accs[ni][0] * inv0, accs[ni][1] * inv0);
            *reinterpret_cast<__half2*>(P + (wms + gid + 8) * 80 + c0) =
                __floats2half2_rn(accs[ni][2] * inv1, accs[ni][3] * inv1);
        }
    }
    __syncthreads();

    {
        const int wm2 = (warp & 3) * 32;
        const int wn2 = (warp >> 2) * 64;
        float acco[2][8][4];
        #pragma unroll
        for (int mi = 0; mi < 2; mi++)
            #pragma unroll
            for (int ni = 0; ni < 8; ni++)
                #pragma unroll
                for (int j = 0; j < 4; j++) acco[mi][ni][j] = 0.f;

        #pragma unroll
        for (int kk = 0; kk < 80; kk += 16) {
            uint32_t afr[2][4], bfr[8][2];
            #pragma unroll
            for (int mi = 0; mi < 2; mi++) {
                uint32_t addr = sb + FQ_SV + (uint32_t)((wm2 + mi * 16 + (tl & 1) * 8 + rr) * 80
                                                        + kk + (tl >> 1) * 8) * 2;
                LDSM_X4(afr[mi][0], afr[mi][1], afr[mi][2], afr[mi][3], addr);
            }
            #pragma unroll
            for (int np = 0; np < 4; np++) {
                uint32_t addr = sb + FQ_SK + (uint32_t)((wn2 + np * 16 + (tl >> 1) * 8 + rr) * 80
                                                        + kk + (tl & 1) * 8) * 2;
                LDSM_X4(bfr[2*np][0], bfr[2*np][1], bfr[2*np+1][0], bfr[2*np+1][1], addr);
            }
            #pragma unroll
            for (int mi = 0; mi < 2; mi++)
                #pragma unroll
                for (int ni = 0; ni < 8; ni++)
                    mma_f16(acco[mi][ni], afr[mi], bfr[ni]);
        }

        __half* Ob = O + (size_t)b * CC * NN + (size_t)(h * HD) * NN;
        #pragma unroll
        for (int mi = 0; mi < 2; mi++) {
            int r0 = wm2 + mi * 16 + gid;
            #pragma unroll
            for (int ni = 0; ni < 8; ni++) {
                int c0 = n0 + wn2 + ni * 8 + 2 * tig;
                Ob[(size_t)r0 * NN + c0]           = __float2half(acco[mi][ni][0]);
                Ob[(size_t)r0 * NN + c0 + 1]       = __float2half(acco[mi][ni][1]);
                Ob[(size_t)(r0 + 8) * NN + c0]     = __float2half(acco[mi][ni][2]);
                Ob[(size_t)(r0 + 8) * NN + c0 + 1] = __float2half(acco[mi][ni][3]);
            }
        }
    }
}

// ===========================================================================
// Small generic GEMM — KV projection only (unchanged).
// ===========================================================================
#define STAGE_B 20480

template <bool AT, bool BT, int OM>
__global__ __launch_bounds__(256, 2)
void hgemm(const __half* __restrict__ A, const __half* __restrict__ B,
           void* __restrict__ Cv, const float* __restrict__ bias,
           int M, int N, int K,
           long long sA, long long sB, long long ldc,
           long long sAb, long long sAh, long long sBb, long long sBh,
           long long sCb, long long sCh, int nh, float alpha,
           int Ka, int Bbound, int nvalid)
{
    extern __shared__ char smem[];
    const uint32_t sb = smem_u32(smem);

    const int tid  = threadIdx.x;
    const int lane = tid & 31;
    const int warp = tid >> 5;
    const int wm = (warp & 3) * 32;
    const int wn = (warp >> 2) * 64;
    const int gid = lane >> 2;
    const int tig = lane & 3;
    const int tl  = lane >> 3;
    const int rr  = lane & 7;

    const int z = blockIdx.z;
    const int b = z / nh;
    const int h = z - b * nh;
    const __half* Ab = A + (size_t)b * sAb + (size_t)h * sAh;
    const __half* Bb = B + (size_t)b * sBb + (size_t)h * sBh;

    const int m0 = blockIdx.y * 128;
    const int n0 = blockIdx.x * 128;
    const int nkt = (K + 31) >> 5;

    auto load_tile = [&](int kt, int s) {
        const int k0 = kt << 5;
        const uint32_t aB = sb + (uint32_t)s * STAGE_B;
        const uint32_t bB = aB + 10240;
        #pragma unroll
        for (int i = 0; i < 2; i++) {
            int sg = tid + i * 256;
            if (!AT) {
                int m = sg >> 2, sk = sg & 3;
                CP16(aB + (uint32_t)(m * 40 + sk * 8) * 2,
                     Ab + (size_t)(m0 + m) * sA + k0 + sk * 8,
                     (k0 + sk * 8 < Ka) ? 16 : 0);
            } else {
                int k = sg >> 4, sm = sg & 15;
                CP16(aB + (uint32_t)(k * 136 + sm * 8) * 2,
                     Ab + (size_t)(k0 + k) * sA + m0 + sm * 8, 16);
            }
        }
        #pragma unroll
        for (int i = 0; i < 2; i++) {
            int sg = tid + i * 256;
            if (BT) {
                int k = sg >> 4, sn = sg & 15;
                CP16(bB + (uint32_t)(k * 136 + sn * 8) * 2,
                     Bb + (size_t)(k0 + k) * sB + n0 + sn * 8,
                     (n0 + sn * 8 < Bbound) ? 16 : 0);
            } else {
                int n = sg >> 2, sk = sg & 3;
                CP16(bB + (uint32_t)(n * 40 + sk * 8) * 2,
                     Bb + (size_t)(n0 + n) * sB + k0 + sk * 8,
                     (k0 + sk * 8 < Bbound) ? 16 : 0);
            }
        }
        CP_COMMIT();
    };

    float acc[2][8][4];
    #pragma unroll
    for (int mi = 0; mi < 2; mi++)
        #pragma unroll
        for (int ni = 0; ni < 8; ni++)
            #pragma unroll
            for (int j = 0; j < 4; j++) acc[mi][ni][j] = 0.f;

    load_tile(0, 0);
    if (nkt > 1) load_tile(1, 1); else CP_COMMIT();

    for (int kt = 0; kt < nkt; kt++) {
        CP_WAIT1();
        __syncthreads();
        if (kt + 2 < nkt) load_tile(kt + 2, (kt + 2) % 3);
        else CP_COMMIT();

        const uint32_t aB = sb + (uint32_t)((kt % 3) * STAGE_B);
        const uint32_t bB = aB + 10240;

        #pragma unroll
        for (int kk = 0; kk < 32; kk += 16) {
            uint32_t afr[2][4], bfr[8][2];
            #pragma unroll
            for (int mi = 0; mi < 2; mi++) {
                uint32_t addr;
                if (!AT)
                    addr = aB + (uint32_t)((wm + mi * 16 + (tl & 1) * 8 + rr) * 40
                                           + kk + (tl >> 1) * 8) * 2;
                else
                    addr = aB + (uint32_t)((kk + (tl >> 1) * 8 + rr) * 136
                                           + wm + mi * 16 + (tl & 1) * 8) * 2;
                if (!AT) LDSM_X4 (afr[mi][0], afr[mi][1], afr[mi][2], afr[mi][3], addr);
                else     LDSM_X4T(afr[mi][0], afr[mi][1], afr[mi][2], afr[mi][3], addr);
            }
            #pragma unroll
            for (int np = 0; np < 4; np++) {
                int nb = wn + np * 16;
                uint32_t addr;
                if (BT)
                    addr = bB + (uint32_t)((kk + (tl & 1) * 8 + rr) * 136
                                           + nb + (tl >> 1) * 8) * 2;
                else
                    addr = bB + (uint32_t)((nb + (tl >> 1) * 8 + rr) * 40
                                           + kk + (tl & 1) * 8) * 2;
                if (BT) LDSM_X4T(bfr[2*np][0], bfr[2*np][1], bfr[2*np+1][0], bfr[2*np+1][1], addr);
                else    LDSM_X4 (bfr[2*np][0], bfr[2*np][1], bfr[2*np+1][0], bfr[2*np+1][1], addr);
            }
            #pragma unroll
            for (int mi = 0; mi < 2; mi++)
                #pragma unroll
                for (int ni = 0; ni < 8; ni++)
                    mma_f16(acc[mi][ni], afr[mi], bfr[ni]);
        }
    }

    if (OM == 1) {
        __half* Cb = (__half*)Cv + (size_t)b * sCb + (size_t)h * sCh;
        #pragma unroll
        for (int mi = 0; mi < 2; mi++) {
            int r0 = m0 + wm + mi * 16 + gid;
            float bv0 = bias ? bias[r0]     : 0.f;
            float bv1 = bias ? bias[r0 + 8] : 0.f;
            #pragma unroll
            for (int ni = 0; ni < 8; ni++) {
                int c0 = n0 + wn + ni * 8 + 2 * tig;
                if (c0 < N) {
                    #pragma unroll
                    for (int j = 0; j < 2; j++) {
                        int c = c0 + j;
                        bool v = (c < nvalid);
                        Cb[(size_t)r0 * ldc + c] =
                            __float2half(v ? alpha * acc[mi][ni][j] + bv0 : 0.f);
                        Cb[(size_t)(r0 + 8) * ldc + c] =
                            __float2half(v ? alpha * acc[mi][ni][2 + j] + bv1 : 0.f);
                    }
                }
            }
        }
    }
}

// ---------------------------------------------------------------- converters
#define N4_VX  (NB * CC * NN / 4)
#define N4_WQ  (CC * CC / 4)
#define N4_WKV (2 * CC * CC / 4)

__global__ void f2h_all(const float* __restrict__ Vx, const float* __restrict__ Wq,
                        const float* __restrict__ Wkv, const float* __restrict__ Wp,
                        __half* __restrict__ dVx, __half* __restrict__ dWq,
                        __half* __restrict__ dWkv, __half* __restrict__ dWp)
{
    int i = blockIdx.x * 256 + threadIdx.x;
    const float* s; __half* d; int j;
    if (i < N4_VX)                       { s = Vx;  d = dVx;  j = i; }
    else if (i < N4_VX + N4_WQ)          { s = Wq;  d = dWq;  j = i - N4_VX; }
    else if (i < N4_VX + N4_WQ + N4_WKV) { s = Wkv; d = dWkv; j = i - N4_VX - N4_WQ; }
    else                                 { s = Wp;  d = dWp;  j = i - N4_VX - N4_WQ - N4_WKV; }
    float4 v = reinterpret_cast<const float4*>(s)[j];
    __half2* d2 = reinterpret_cast<__half2*>(d);
    d2[2 * j]     = __floats2half2_rn(v.x, v.y);
    d2[2 * j + 1] = __floats2half2_rn(v.z, v.w);
}
__global__ void f2h_pad77(const float* __restrict__ s, __half* __restrict__ d, int rows)
{
    int r = blockIdx.x, c = threadIdx.x;
    if (c < TP)
        d[(size_t)r * TP + c] = __float2half((c < TT) ? s[(size_t)r * TT + c] : 0.f);
}

// ---------------------------------------------------------------- launch
extern "C" void kernel_launch(void* const* d_in, const int* in_sizes, int n_in,
                              void* d_out, int out_size)
{
    const float* Vx  = (const float*)d_in[0];
    const float* Tx  = (const float*)d_in[1];
    const float* Wq  = (const float*)d_in[2];
    const float* bq  = (const float*)d_in[3];
    const float* Wkv = (const float*)d_in[4];
    const float* bkv = (const float*)d_in[5];
    const float* Wp  = (const float*)d_in[6];
    const float* bp  = (const float*)d_in[7];
    float* Y = (float*)d_out;

    __half *hVx, *hTx, *hWq, *hWkv, *hWp, *hKV, *hO;
    cudaGetSymbolAddress((void**)&hVx, h_Vx);
    cudaGetSymbolAddress((void**)&hTx, h_Tx);
    cudaGetSymbolAddress((void**)&hWq, h_Wq);
    cudaGetSymbolAddress((void**)&hWkv, h_Wkv);
    cudaGetSymbolAddress((void**)&hWp, h_Wp);
    cudaGetSymbolAddress((void**)&hKV, h_KV);
    cudaGetSymbolAddress((void**)&hO,  h_O);

    constexpr int SMEM_SMALL = STAGE_B * 3;   // 61440
    cudaFuncSetAttribute(hgemm<false, true, 1>, cudaFuncAttributeMaxDynamicSharedMemorySize, SMEM_SMALL);
    cudaFuncSetAttribute(hgemm_big<0>, cudaFuncAttributeMaxDynamicSharedMemorySize, BIG_SMEM);
    cudaFuncSetAttribute(fused_qattn, cudaFuncAttributeMaxDynamicSharedMemorySize, BIG_SMEM);

    const float scale = 0.08838834764831843f;  // 1/sqrt(128)

    // 0) fp32 -> fp16
    f2h_all<<<(N4_VX + N4_WQ + N4_WKV + N4_WQ) / 256, 256>>>(
        Vx, Wq, Wkv, Wp, hVx, hWq, hWkv, hWp);
    f2h_pad77<<<NB * CC, 128>>>(Tx, hTx, NB * CC);

    // 1) KV = Wkv @ Tx + bkv : M=2048, N=80(valid 77), K=1024, per-b
    hgemm<false, true, 1><<<dim3(1, 16, NB), 256, SMEM_SMALL>>>(
        hWkv, hTx, hKV, bkv, 2048, TP, CC,
        CC, TP, TP,
        0, 0, (long long)CC * TP, 0,
        (long long)2 * CC * TP, 0, 1, 1.0f, CC, TP, TT);

    // 2) fused Q-projection + attention : per (ntile, h, b)
    fused_qattn<<<dim3(8, NH, NB), 256, BIG_SMEM>>>(
        hWq, hVx, bq, hKV, hO, scale);

    // 3) Y = Wp @ O + bp : per-b, fp32 out  [BIG 128x128x64, 2 CTA/SM]
    hgemm_big<0><<<dim3(8, 8, NB), 256, BIG_SMEM>>>(
        hWp, hO, Y, bp, (long long)CC * NN, (long long)CC * NN);
}